// round 4
// baseline (speedup 1.0000x reference)
#include <cuda_runtime.h>
#include <math.h>

// CT forward projection, two passes:
//  1) transpose volume [x][y][z] -> volT [y][z][x]  (x innermost matches the
//     dominant ray direction: consecutive samples share cache lines)
//  2) warp-per-ray projection with 4 segments/lane (MLP=4), branchless,
//     folded affine transform q(t) = S + t*D.

#define VOL_MAX_N 256
__device__ float g_volT[(size_t)VOL_MAX_N * VOL_MAX_N * VOL_MAX_N];

// ---------------------------------------------------------------- transpose
#define TDIM 32
__global__ __launch_bounds__(256)
void transpose_kernel(const float* __restrict__ src, int n)
{
    __shared__ float tile[TDIM][TDIM + 1];
    const int x0 = blockIdx.x * TDIM;
    const int z0 = blockIdx.y * TDIM;
    const int y  = blockIdx.z;
    const int tx = threadIdx.x;     // 0..31
    const int ty = threadIdx.y;     // 0..7
    const size_t n2 = (size_t)n * n;

    #pragma unroll
    for (int i = ty; i < TDIM; i += 8) {
        const int x = x0 + i, z = z0 + tx;
        if (x < n && z < n)
            tile[i][tx] = src[(size_t)x * n2 + (size_t)y * n + z];
    }
    __syncthreads();
    #pragma unroll
    for (int i = ty; i < TDIM; i += 8) {
        const int z = z0 + i, x = x0 + tx;
        if (z < n && x < n)
            g_volT[(size_t)y * n2 + (size_t)z * n + x] = tile[tx][i];
    }
}

// ---------------------------------------------------------------- projector
// TRANSPOSED=1: gather from g_volT with idx=(y*n+z)*n+x
// TRANSPOSED=0: gather from vol   with idx=(x*n+y)*n+z (fallback, n>VOL_MAX_N)
template <int TRANSPOSED>
__global__ __launch_bounds__(256)
void ctproj_kernel(const float* __restrict__ vol,
                   const float* __restrict__ tvals,
                   const float* __restrict__ src,
                   const float* __restrict__ dst,
                   const float* __restrict__ Mmat,
                   const float* __restrict__ bvec,
                   float* __restrict__ out,
                   int R, int K, int n)
{
    const int warp = (blockIdx.x * blockDim.x + threadIdx.x) >> 5;
    const int lane = threadIdx.x & 31;
    if (warp >= R) return;
    const int r = warp;

    const float sx = __ldg(src + 3 * r + 0);
    const float sy = __ldg(src + 3 * r + 1);
    const float sz = __ldg(src + 3 * r + 2);
    const float dx = __ldg(dst + 3 * r + 0) - sx;
    const float dy = __ldg(dst + 3 * r + 1) - sy;
    const float dz = __ldg(dst + 3 * r + 2) - sz;
    const float ray_len = sqrtf(dx * dx + dy * dy + dz * dz);

    const float m00 = __ldg(Mmat + 0), m01 = __ldg(Mmat + 1), m02 = __ldg(Mmat + 2);
    const float m10 = __ldg(Mmat + 3), m11 = __ldg(Mmat + 4), m12 = __ldg(Mmat + 5);
    const float m20 = __ldg(Mmat + 6), m21 = __ldg(Mmat + 7), m22 = __ldg(Mmat + 8);
    const float b0 = __ldg(bvec + 0), b1 = __ldg(bvec + 1), b2 = __ldg(bvec + 2);

    // q(t) = S + t * D
    const float Sx = m00 * sx + m01 * sy + m02 * sz + b0;
    const float Sy = m10 * sx + m11 * sy + m12 * sz + b1;
    const float Sz = m20 * sx + m21 * sy + m22 * sz + b2;
    const float Dx = m00 * dx + m01 * dy + m02 * dz;
    const float Dy = m10 * dx + m11 * dy + m12 * dz;
    const float Dz = m20 * dx + m21 * dy + m22 * dz;

    const float* __restrict__ trow = tvals + (size_t)r * K;
    const int nseg = K - 1;
    const int nm1  = n - 1;
    const unsigned nu = (unsigned)n;
    const unsigned FULL = 0xffffffffu;

    float acc0 = 0.0f, acc1 = 0.0f;

    for (int base = 0; base < nseg; base += 128) {
        const int i = base + 4 * lane;
        const float4 v = *(const float4*)(trow + i);

        // Uniform early exit on sorted +inf tail.
        const float lead = __shfl_sync(FULL, v.x, 0);
        if (!(lead < 1e30f)) break;

        const int eidx = (base + 128 < K) ? (base + 128) : (K - 1);
        const float extra = __ldg(trow + eidx);
        float t4 = __shfl_down_sync(FULL, v.x, 1);
        if (lane == 31) t4 = extra;

        const float t[5] = { v.x, v.y, v.z, v.w, t4 };

        int   idx[4];
        float w[4];

        #pragma unroll
        for (int j = 0; j < 4; ++j) {
            const int  k     = i + j;
            const bool valid = (k < nseg) && (t[j + 1] < 1e30f);

            const float seg = (t[j + 1] - t[j]) * ray_len;
            const float tm  = 0.5f * (t[j] + t[j + 1]);

            const float qx = fmaf(tm, Dx, Sx);
            const float qy = fmaf(tm, Dy, Sy);
            const float qz = fmaf(tm, Dz, Sz);

            const int ix = (int)floorf(qx);
            const int iy = (int)floorf(qy);
            const int iz = (int)floorf(qz);

            const bool inb = valid &&
                             ((unsigned)ix < nu) &&
                             ((unsigned)iy < nu) &&
                             ((unsigned)iz < nu);

            const int cx = min(max(ix, 0), nm1);
            const int cy = min(max(iy, 0), nm1);
            const int cz = min(max(iz, 0), nm1);

            idx[j] = TRANSPOSED ? ((cy * n + cz) * n + cx)
                                : ((cx * n + cy) * n + cz);
            w[j]   = inb ? seg : 0.0f;
        }

        float g0, g1, g2, g3;
        if (TRANSPOSED) {
            g0 = __ldg(g_volT + idx[0]);
            g1 = __ldg(g_volT + idx[1]);
            g2 = __ldg(g_volT + idx[2]);
            g3 = __ldg(g_volT + idx[3]);
        } else {
            g0 = __ldg(vol + idx[0]);
            g1 = __ldg(vol + idx[1]);
            g2 = __ldg(vol + idx[2]);
            g3 = __ldg(vol + idx[3]);
        }

        acc0 = fmaf(g0, w[0], acc0);
        acc1 = fmaf(g1, w[1], acc1);
        acc0 = fmaf(g2, w[2], acc0);
        acc1 = fmaf(g3, w[3], acc1);
    }

    float acc = acc0 + acc1;
    #pragma unroll
    for (int off = 16; off > 0; off >>= 1)
        acc += __shfl_down_sync(FULL, acc, off);

    if (lane == 0) out[r] = acc;
}

extern "C" void kernel_launch(void* const* d_in, const int* in_sizes, int n_in,
                              void* d_out, int out_size)
{
    const float* volume = (const float*)d_in[0];
    const float* tvals  = (const float*)d_in[1];
    const float* src    = (const float*)d_in[2];
    const float* dst    = (const float*)d_in[3];
    const float* Mmat   = (const float*)d_in[4];
    const float* bvec   = (const float*)d_in[5];
    float* out = (float*)d_out;

    const int R = in_sizes[2] / 3;
    const int K = in_sizes[1] / R;
    int n = (int)lroundf(cbrtf((float)in_sizes[0]));
    while ((long long)n * n * n < (long long)in_sizes[0]) n++;
    while ((long long)n * n * n > (long long)in_sizes[0]) n--;

    const int threads = 256;
    const int blocks = (R * 32 + threads - 1) / threads;

    if (n <= VOL_MAX_N) {
        dim3 tgrid((n + TDIM - 1) / TDIM, (n + TDIM - 1) / TDIM, n);
        dim3 tblk(32, 8);
        transpose_kernel<<<tgrid, tblk>>>(volume, n);
        ctproj_kernel<1><<<blocks, threads>>>(volume, tvals, src, dst, Mmat,
                                              bvec, out, R, K, n);
    } else {
        ctproj_kernel<0><<<blocks, threads>>>(volume, tvals, src, dst, Mmat,
                                              bvec, out, R, K, n);
    }
}

// round 5
// speedup vs baseline: 1.2400x; 1.2400x over previous
#include <cuda_runtime.h>
#include <cuda_fp16.h>
#include <math.h>

// CT forward projection, two passes:
//  1) transpose+quantize volume [x][y][z] fp32 -> volT [y][z][x] fp16
//     (x innermost = guaranteed-traversal axis; fp16 halves gather bytes and
//      makes the 32MB volT fully L2-resident)
//  2) warp-per-ray projection, 4 segments/lane (MLP=4), branchless,
//     folded affine transform q(t) = S + t*D, n=256 shift indexing.

#define VOL_N 256
__device__ __half g_volT[(size_t)VOL_N * VOL_N * VOL_N];

// ---------------------------------------------------------------- transpose
// For each y: out2d[z][x] = in2d[x][z].  Tile 32x(x) x 32(z), threads (8,32).
__global__ __launch_bounds__(256)
void transpose_kernel(const float* __restrict__ src)
{
    __shared__ float tile[32][33];
    const int x0 = blockIdx.x * 32;
    const int z0 = blockIdx.y * 32;
    const int y  = blockIdx.z;
    const int tx = threadIdx.x;   // 0..7  (float4 chunk)
    const int ty = threadIdx.y;   // 0..31

    // Phase 1: load in[x0+ty][y][z0+4tx .. +3] as float4 (coalesced in z)
    {
        const size_t off = ((size_t)(x0 + ty) << 16) | ((size_t)y << 8) | (size_t)(z0 + 4 * tx);
        const float4 v = *(const float4*)(src + off);
        tile[ty][4 * tx + 0] = v.x;
        tile[ty][4 * tx + 1] = v.y;
        tile[ty][4 * tx + 2] = v.z;
        tile[ty][4 * tx + 3] = v.w;
    }
    __syncthreads();

    // Phase 2: out[y][z0+ty][x0+4tx .. +3] = tile[4tx+k][ty] (conflict-free)
    {
        const float a = tile[4 * tx + 0][ty];
        const float b = tile[4 * tx + 1][ty];
        const float c = tile[4 * tx + 2][ty];
        const float d = tile[4 * tx + 3][ty];
        __half2 h01 = __floats2half2_rn(a, b);
        __half2 h23 = __floats2half2_rn(c, d);
        const size_t off = ((size_t)y << 16) | ((size_t)(z0 + ty) << 8) | (size_t)(x0 + 4 * tx);
        __half2* p = (__half2*)(g_volT + off);
        p[0] = h01;
        p[1] = h23;
    }
}

// ---------------------------------------------------------------- projector
// SPECIAL=1: n==256, gather fp16 from g_volT with idx=(y<<16)|(z<<8)|x.
// SPECIAL=0: generic fallback, fp32 gathers from original-layout volume.
template <int SPECIAL>
__global__ __launch_bounds__(256)
void ctproj_kernel(const float* __restrict__ vol,
                   const float* __restrict__ tvals,
                   const float* __restrict__ src,
                   const float* __restrict__ dst,
                   const float* __restrict__ Mmat,
                   const float* __restrict__ bvec,
                   float* __restrict__ out,
                   int R, int K, int n)
{
    const int warp = (blockIdx.x * blockDim.x + threadIdx.x) >> 5;
    const int lane = threadIdx.x & 31;
    if (warp >= R) return;
    const int r = warp;

    const float sx = __ldg(src + 3 * r + 0);
    const float sy = __ldg(src + 3 * r + 1);
    const float sz = __ldg(src + 3 * r + 2);
    const float dx = __ldg(dst + 3 * r + 0) - sx;
    const float dy = __ldg(dst + 3 * r + 1) - sy;
    const float dz = __ldg(dst + 3 * r + 2) - sz;
    const float ray_len = sqrtf(dx * dx + dy * dy + dz * dz);

    const float m00 = __ldg(Mmat + 0), m01 = __ldg(Mmat + 1), m02 = __ldg(Mmat + 2);
    const float m10 = __ldg(Mmat + 3), m11 = __ldg(Mmat + 4), m12 = __ldg(Mmat + 5);
    const float m20 = __ldg(Mmat + 6), m21 = __ldg(Mmat + 7), m22 = __ldg(Mmat + 8);
    const float b0 = __ldg(bvec + 0), b1 = __ldg(bvec + 1), b2 = __ldg(bvec + 2);

    // q(t) = S + t * D
    const float Sx = m00 * sx + m01 * sy + m02 * sz + b0;
    const float Sy = m10 * sx + m11 * sy + m12 * sz + b1;
    const float Sz = m20 * sx + m21 * sy + m22 * sz + b2;
    const float Dx = m00 * dx + m01 * dy + m02 * dz;
    const float Dy = m10 * dx + m11 * dy + m12 * dz;
    const float Dz = m20 * dx + m21 * dy + m22 * dz;

    const float* __restrict__ trow = tvals + (size_t)r * K;
    const int nseg = K - 1;
    const int nn   = SPECIAL ? VOL_N : n;
    const int nm1  = nn - 1;
    const unsigned nu = (unsigned)nn;
    const unsigned FULL = 0xffffffffu;

    float acc0 = 0.0f, acc1 = 0.0f;

    for (int base = 0; base < nseg; base += 128) {
        const int i = base + 4 * lane;
        const float4 v = *(const float4*)(trow + i);

        // Uniform early exit on sorted +inf tail.
        const float lead = __shfl_sync(FULL, v.x, 0);
        if (!(lead < 1e30f)) break;

        const int eidx = (base + 128 < K) ? (base + 128) : (K - 1);
        const float extra = __ldg(trow + eidx);
        float t4 = __shfl_down_sync(FULL, v.x, 1);
        if (lane == 31) t4 = extra;

        const float t[5] = { v.x, v.y, v.z, v.w, t4 };

        int   idx[4];
        float w[4];

        #pragma unroll
        for (int j = 0; j < 4; ++j) {
            const int  k     = i + j;
            const bool valid = (k < nseg) && (t[j + 1] < 1e30f);

            const float seg = (t[j + 1] - t[j]) * ray_len;
            const float tm  = 0.5f * (t[j] + t[j + 1]);

            const float qx = fmaf(tm, Dx, Sx);
            const float qy = fmaf(tm, Dy, Sy);
            const float qz = fmaf(tm, Dz, Sz);

            const int ix = __float2int_rd(qx);
            const int iy = __float2int_rd(qy);
            const int iz = __float2int_rd(qz);

            const bool inb = valid &&
                             ((unsigned)ix < nu) &&
                             ((unsigned)iy < nu) &&
                             ((unsigned)iz < nu);

            const int cx = min(max(ix, 0), nm1);
            const int cy = min(max(iy, 0), nm1);
            const int cz = min(max(iz, 0), nm1);

            idx[j] = SPECIAL ? ((cy << 16) | (cz << 8) | cx)
                             : ((cx * nn + cy) * nn + cz);
            w[j]   = inb ? seg : 0.0f;
        }

        float g0, g1, g2, g3;
        if (SPECIAL) {
            g0 = __half2float(__ldg(g_volT + idx[0]));
            g1 = __half2float(__ldg(g_volT + idx[1]));
            g2 = __half2float(__ldg(g_volT + idx[2]));
            g3 = __half2float(__ldg(g_volT + idx[3]));
        } else {
            g0 = __ldg(vol + idx[0]);
            g1 = __ldg(vol + idx[1]);
            g2 = __ldg(vol + idx[2]);
            g3 = __ldg(vol + idx[3]);
        }

        acc0 = fmaf(g0, w[0], acc0);
        acc1 = fmaf(g1, w[1], acc1);
        acc0 = fmaf(g2, w[2], acc0);
        acc1 = fmaf(g3, w[3], acc1);
    }

    float acc = acc0 + acc1;
    #pragma unroll
    for (int off = 16; off > 0; off >>= 1)
        acc += __shfl_down_sync(FULL, acc, off);

    if (lane == 0) out[r] = acc;
}

extern "C" void kernel_launch(void* const* d_in, const int* in_sizes, int n_in,
                              void* d_out, int out_size)
{
    const float* volume = (const float*)d_in[0];
    const float* tvals  = (const float*)d_in[1];
    const float* src    = (const float*)d_in[2];
    const float* dst    = (const float*)d_in[3];
    const float* Mmat   = (const float*)d_in[4];
    const float* bvec   = (const float*)d_in[5];
    float* out = (float*)d_out;

    const int R = in_sizes[2] / 3;
    const int K = in_sizes[1] / R;
    int n = (int)lroundf(cbrtf((float)in_sizes[0]));
    while ((long long)n * n * n < (long long)in_sizes[0]) n++;
    while ((long long)n * n * n > (long long)in_sizes[0]) n--;

    const int threads = 256;
    const int blocks = (R * 32 + threads - 1) / threads;

    if (n == VOL_N) {
        dim3 tgrid(VOL_N / 32, VOL_N / 32, VOL_N);
        dim3 tblk(8, 32);
        transpose_kernel<<<tgrid, tblk>>>(volume);
        ctproj_kernel<1><<<blocks, threads>>>(volume, tvals, src, dst, Mmat,
                                              bvec, out, R, K, n);
    } else {
        ctproj_kernel<0><<<blocks, threads>>>(volume, tvals, src, dst, Mmat,
                                              bvec, out, R, K, n);
    }
}